// round 10
// baseline (speedup 1.0000x reference)
#include <cuda_runtime.h>
#include <cuda_bf16.h>
#include <cstdint>

#define B_  16
#define H_  8
#define L_  1024
#define DK_ 64
#define BH_ 128
#define NROWS_ (BH_ * L_)
#define SCALE_ 0.125f

// ---------------------------------------------------------------------------
// Device scratch
// ---------------------------------------------------------------------------
__device__ float g_l1[(size_t)BH_ * L_ * L_];
__device__ __nv_bfloat16 g_cath[(size_t)BH_ * L_ * 128];  // [bh][row][Q|K]
__device__ __nv_bfloat16 g_catl[(size_t)BH_ * L_ * 128];
__device__ __nv_bfloat16 g_Wh[(size_t)H_ * L_ * 128];     // pre-scaled by 0.125
__device__ __nv_bfloat16 g_Wl[(size_t)H_ * L_ * 128];
__device__ __nv_bfloat16 g_Vth[(size_t)BH_ * DK_ * L_];   // [bh][d][k]
__device__ __nv_bfloat16 g_Vtl[(size_t)BH_ * DK_ * L_];
__device__ float2 g_stat1[NROWS_];                        // per row (M, 1/S)
__device__ float2 g_stat2[NROWS_];

// ---------------------------------------------------------------------------
// Helpers
// ---------------------------------------------------------------------------
__device__ __forceinline__ uint32_t smem_u32(const void* p) {
    uint32_t a;
    asm("{ .reg .u64 t; cvta.to.shared.u64 t, %1; cvt.u32.u64 %0, t; }" : "=r"(a) : "l"(p));
    return a;
}
__device__ __forceinline__ void cp16(uint32_t dst, const void* src) {
    asm volatile("cp.async.cg.shared.global [%0], [%1], 16;" :: "r"(dst), "l"(src));
}
#define CP_COMMIT() asm volatile("cp.async.commit_group;" ::: "memory")
#define CP_WAIT(N)  asm volatile("cp.async.wait_group %0;" :: "n"(N) : "memory")

__device__ __forceinline__ void mma_bf16(float (&c)[4], const uint32_t (&a)[4],
                                         const uint32_t b0, const uint32_t b1) {
    asm volatile(
        "mma.sync.aligned.m16n8k16.row.col.f32.bf16.bf16.f32 "
        "{%0,%1,%2,%3}, {%4,%5,%6,%7}, {%8,%9}, {%0,%1,%2,%3};\n"
        : "+f"(c[0]), "+f"(c[1]), "+f"(c[2]), "+f"(c[3])
        : "r"(a[0]), "r"(a[1]), "r"(a[2]), "r"(a[3]), "r"(b0), "r"(b1));
}

__device__ __forceinline__ void ldm_x4(uint32_t (&r)[4], uint32_t addr) {
    asm volatile("ldmatrix.sync.aligned.m8n8.x4.shared.b16 {%0,%1,%2,%3}, [%4];"
                 : "=r"(r[0]), "=r"(r[1]), "=r"(r[2]), "=r"(r[3]) : "r"(addr));
}

__device__ __forceinline__ void split_pack4(const float* f, uint2& hp, uint2& lp) {
    unsigned short* hw = (unsigned short*)&hp;
    unsigned short* lw = (unsigned short*)&lp;
    #pragma unroll
    for (int k = 0; k < 4; k++) {
        __nv_bfloat16 hb = __float2bfloat16(f[k]);
        float r = f[k] - __bfloat162float(hb);
        hw[k] = __bfloat16_as_ushort(hb);
        lw[k] = __bfloat16_as_ushort(__float2bfloat16(r));
    }
}

// ---------------------------------------------------------------------------
// Prep kernels (unchanged)
// ---------------------------------------------------------------------------
__global__ void cat_kernel(const float* __restrict__ Q, const float* __restrict__ K) {
    int tid = blockIdx.x * blockDim.x + threadIdx.x;
    int q = tid & 31;
    size_t row = (size_t)(tid >> 5);
    const float* src = (q < 16) ? (Q + row * 64 + q * 4)
                                : (K + row * 64 + (q - 16) * 4);
    int col = (q < 16) ? q * 4 : 64 + (q - 16) * 4;
    float4 v = *(const float4*)src;
    float f[4] = {v.x, v.y, v.z, v.w};
    uint2 hp, lp;
    split_pack4(f, hp, lp);
    *(uint2*)(g_cath + row * 128 + col) = hp;
    *(uint2*)(g_catl + row * 128 + col) = lp;
}

__global__ void wsplit_kernel(const float* __restrict__ W) {
    int tid = blockIdx.x * blockDim.x + threadIdx.x;
    float4 v = ((const float4*)W)[tid];
    float f[4] = {v.x * SCALE_, v.y * SCALE_, v.z * SCALE_, v.w * SCALE_};
    uint2 hp, lp;
    split_pack4(f, hp, lp);
    *(uint2*)(g_Wh + (size_t)tid * 4) = hp;
    *(uint2*)(g_Wl + (size_t)tid * 4) = lp;
}

__global__ void vtrans_kernel(const float* __restrict__ V) {
    __shared__ float tile[64][65];
    int bh = blockIdx.y, k0 = blockIdx.x << 6, t = threadIdx.x;
    const float* src = V + ((size_t)bh * L_ + k0) * DK_;
    #pragma unroll
    for (int i = 0; i < 16; i++) {
        int lin = t + i * 256;
        int r = lin >> 6, d = lin & 63;
        tile[r][d] = src[r * DK_ + d];
    }
    __syncthreads();
    #pragma unroll
    for (int i = 0; i < 16; i++) {
        int lin = t + i * 256;
        int d = lin >> 6, c = lin & 63;
        float x = tile[c][d];
        __nv_bfloat16 hb = __float2bfloat16(x);
        float r = x - __bfloat162float(hb);
        size_t o = ((size_t)bh * DK_ + d) * L_ + k0 + c;
        g_Vth[o] = hb;
        g_Vtl[o] = __float2bfloat16(r);
    }
}

// ---------------------------------------------------------------------------
// n-persistent logits GEMM + running row softmax stats (R9 proven config).
// 256 threads, grouped ldmatrix frags, __stcs tile stores (new).
// ---------------------------------------------------------------------------
template <int MODE>
__global__ void __launch_bounds__(256) mm_logits_kernel(float* __restrict__ l2out) {
    constexpr int KD = (MODE == 0) ? 64 : 128;
    constexpr int ST = KD + 8;
    constexpr int TSZ = 128 * ST;
    extern __shared__ __align__(16) __nv_bfloat16 sm[];
    __nv_bfloat16* sAh = sm;
    __nv_bfloat16* sAl = sm + TSZ;
    __nv_bfloat16* sB0 = sm + 2 * TSZ;
    __nv_bfloat16* sB1 = sm + 4 * TSZ;
    __shared__ float2 sStat[2][128];

    const int t = threadIdx.x;
    const int bh = blockIdx.y, h = bh & (H_ - 1);
    const int q0 = blockIdx.x << 7;

    const __nv_bfloat16 *Ah, *Al, *Bh, *Bl;
    if (MODE == 0) {
        size_t base = (size_t)bh * L_ * 128;
        Ah = g_cath + base + (size_t)q0 * 128;
        Al = g_catl + base + (size_t)q0 * 128;
        Bh = g_cath + base + 64;
        Bl = g_catl + base + 64;
    } else {
        Ah = g_Wh + ((size_t)h * L_ + q0) * 128;
        Al = g_Wl + ((size_t)h * L_ + q0) * 128;
        Bh = g_cath + (size_t)bh * L_ * 128;
        Bl = g_catl + (size_t)bh * L_ * 128;
    }

    constexpr int CPR = KD / 8;
    constexpr int ACH = 128 * CPR;

    const uint32_t uA = smem_u32(sm);
    const uint32_t uB0 = smem_u32(sB0);
    const uint32_t uB1 = smem_u32(sB1);

    #pragma unroll
    for (int i = 0; i < ACH / 256; i++) {
        int lin = t + i * 256;
        int row = lin / CPR, pc = lin % CPR;
        cp16(uA + (uint32_t)((row * ST + pc * 8) * 2), Ah + (size_t)row * 128 + pc * 8);
        cp16(uA + (uint32_t)((TSZ + row * ST + pc * 8) * 2), Al + (size_t)row * 128 + pc * 8);
    }
    #pragma unroll
    for (int i = 0; i < ACH / 256; i++) {
        int lin = t + i * 256;
        int row = lin / CPR, pc = lin % CPR;
        cp16(uB0 + (uint32_t)((row * ST + pc * 8) * 2), Bh + (size_t)row * 128 + pc * 8);
        cp16(uB0 + (uint32_t)((TSZ + row * ST + pc * 8) * 2), Bl + (size_t)row * 128 + pc * 8);
    }
    CP_COMMIT();

    const int w = t >> 5, lane = t & 31;
    const int wm = (w >> 1) << 5;          // 0,32,64,96
    const int wn = (w & 1) << 6;           // 0,64
    const int gid = lane >> 2, tig = lane & 3;

    const int rowA = wm + (lane & 15);
    const int kofA = (lane >> 4) << 3;
    const int nrB = wn + ((lane >> 4) << 3) + (lane & 7);
    const int kofB = ((lane >> 3) & 1) << 3;

    const uint32_t uAh = smem_u32(sAh), uAl = smem_u32(sAl);

    float rm[4] = {-1e30f, -1e30f, -1e30f, -1e30f};
    float rs[4] = {0.f, 0.f, 0.f, 0.f};

    float* out = (MODE == 0) ? g_l1 : l2out;

    for (int nt = 0; nt < 8; nt++) {
        const int n0 = nt << 7;
        if (nt < 7) {
            const uint32_t uBn = (nt & 1) ? uB0 : uB1;
            const size_t nb = (size_t)(n0 + 128) * 128;
            #pragma unroll
            for (int i = 0; i < ACH / 256; i++) {
                int lin = t + i * 256;
                int row = lin / CPR, pc = lin % CPR;
                cp16(uBn + (uint32_t)((row * ST + pc * 8) * 2), Bh + nb + (size_t)row * 128 + pc * 8);
                cp16(uBn + (uint32_t)((TSZ + row * ST + pc * 8) * 2), Bl + nb + (size_t)row * 128 + pc * 8);
            }
            CP_COMMIT();
            CP_WAIT(1);
        } else {
            CP_WAIT(0);
        }
        __syncthreads();

        const uint32_t uBh = (nt & 1) ? uB1 : uB0;
        const uint32_t uBl = uBh + TSZ * 2;

        float acc[2][8][4] = {};
        #pragma unroll
        for (int k0 = 0; k0 < KD; k0 += 16) {
            uint32_t ah[2][4], al[2][4];
            #pragma unroll
            for (int i = 0; i < 2; i++) {
                uint32_t aoff = (uint32_t)(((rowA + i * 16) * ST + k0 + kofA) * 2);
                ldm_x4(ah[i], uAh + aoff);
                ldm_x4(al[i], uAl + aoff);
            }
            uint32_t bh4[4][4], bl4[4][4];
            #pragma unroll
            for (int p = 0; p < 4; p++) {
                uint32_t boff = (uint32_t)(((nrB + p * 16) * ST + k0 + kofB) * 2);
                ldm_x4(bh4[p], uBh + boff);
                ldm_x4(bl4[p], uBl + boff);
            }
            #pragma unroll
            for (int i = 0; i < 2; i++)
                #pragma unroll
                for (int j = 0; j < 8; j++) {
                    const int p = j >> 1, q = (j & 1) << 1;
                    mma_bf16(acc[i][j], ah[i], bh4[p][q], bh4[p][q + 1]);
                    mma_bf16(acc[i][j], ah[i], bl4[p][q], bl4[p][q + 1]);
                    mma_bf16(acc[i][j], al[i], bh4[p][q], bh4[p][q + 1]);
                }
        }

        if (MODE == 0) {
            #pragma unroll
            for (int i = 0; i < 2; i++)
                #pragma unroll
                for (int j = 0; j < 8; j++)
                    #pragma unroll
                    for (int c = 0; c < 4; c++)
                        acc[i][j][c] *= SCALE_;
        }

        #pragma unroll
        for (int i = 0; i < 2; i++) {
            float mlo = -1e30f, mhi = -1e30f;
            #pragma unroll
            for (int j = 0; j < 8; j++) {
                mlo = fmaxf(mlo, fmaxf(acc[i][j][0], acc[i][j][1]));
                mhi = fmaxf(mhi, fmaxf(acc[i][j][2], acc[i][j][3]));
            }
            #pragma unroll
            for (int o = 1; o <= 2; o <<= 1) {
                mlo = fmaxf(mlo, __shfl_xor_sync(0xffffffffu, mlo, o));
                mhi = fmaxf(mhi, __shfl_xor_sync(0xffffffffu, mhi, o));
            }
            float slo = 0.f, shi = 0.f;
            #pragma unroll
            for (int j = 0; j < 8; j++) {
                slo += __expf(acc[i][j][0] - mlo) + __expf(acc[i][j][1] - mlo);
                shi += __expf(acc[i][j][2] - mhi) + __expf(acc[i][j][3] - mhi);
            }
            #pragma unroll
            for (int o = 1; o <= 2; o <<= 1) {
                slo += __shfl_xor_sync(0xffffffffu, slo, o);
                shi += __shfl_xor_sync(0xffffffffu, shi, o);
            }
            float nm = fmaxf(rm[i * 2], mlo);
            rs[i * 2] = rs[i * 2] * __expf(rm[i * 2] - nm) + slo * __expf(mlo - nm);
            rm[i * 2] = nm;
            nm = fmaxf(rm[i * 2 + 1], mhi);
            rs[i * 2 + 1] = rs[i * 2 + 1] * __expf(rm[i * 2 + 1] - nm) + shi * __expf(mhi - nm);
            rm[i * 2 + 1] = nm;
        }

        // Store logits tile (streaming — consumed much later, keep L2 for cat/W)
        #pragma unroll
        for (int i = 0; i < 2; i++) {
            #pragma unroll
            for (int j = 0; j < 8; j++) {
                int m = q0 + wm + i * 16 + gid;
                int n = n0 + wn + j * 8 + tig * 2;
                __stcs((float2*)(out + ((size_t)bh * L_ + m) * L_ + n),
                       make_float2(acc[i][j][0], acc[i][j][1]));
                __stcs((float2*)(out + ((size_t)bh * L_ + m + 8) * L_ + n),
                       make_float2(acc[i][j][2], acc[i][j][3]));
            }
        }
        __syncthreads();
    }

    if (tig == 0) {
        int slot = (w & 1);
        #pragma unroll
        for (int i = 0; i < 2; i++) {
            sStat[slot][wm + i * 16 + gid] = make_float2(rm[i * 2], rs[i * 2]);
            sStat[slot][wm + i * 16 + 8 + gid] = make_float2(rm[i * 2 + 1], rs[i * 2 + 1]);
        }
    }
    __syncthreads();
    if (t < 128) {
        float2 a = sStat[0][t], b = sStat[1][t];
        float M = fmaxf(a.x, b.x);
        float S = a.y * __expf(a.x - M) + b.y * __expf(b.x - M);
        float2* st = (MODE == 0) ? g_stat1 : g_stat2;
        st[bh * L_ + q0 + t] = make_float2(M, 1.f / S);
    }
}

// ---------------------------------------------------------------------------
// Fused softmax+AV: 64-row q-tiles, 2 CTAs/SM for cross-CTA phase overlap.
// smem: raw l1/l2 double-buffered (64KB), V single (18.4KB), split (18.4KB).
// Schedule: issue V(kt) -> wait raw(kt) -> transform -> prefetch raw(kt+1)
//           -> wait V(kt) -> sync -> MMA -> sync.
// ---------------------------------------------------------------------------
#define FRAW1_(b) ((b) * 32768)
#define FRAW2_(b) ((b) * 32768 + 16384)
#define FVH_      65536
#define FVL_      (65536 + 9216)
#define FSAH_     83968
#define FSAL_     (83968 + 9216)
#define FSMEM_    102400

__global__ void __launch_bounds__(512) fused_attn_av_kernel(float* __restrict__ attn,
                                                            float* __restrict__ ctx) {
    constexpr int ST = 72;
    extern __shared__ __align__(16) char smb[];
    __shared__ float sStat[256];

    const int t = threadIdx.x;
    const int bh = blockIdx.y;
    const int q0 = blockIdx.x << 6;               // 64-row tiles
    const uint32_t ub = smem_u32(smb);

    if (t < 64) {
        float2 s1 = g_stat1[bh * L_ + q0 + t];
        float2 s2 = g_stat2[bh * L_ + q0 + t];
        sStat[t] = s1.x; sStat[64 + t] = s1.y;
        sStat[128 + t] = s2.x; sStat[192 + t] = s2.y;
    }

    const float* l1base = g_l1 + ((size_t)bh * L_ + q0) * L_;
    float* l2base = attn + ((size_t)bh * L_ + q0) * L_;

    // Prefetch raw(0): 2 branches x 1024 16B chunks = 4/thread
    #pragma unroll
    for (int i = 0; i < 4; i++) {
        int lin = t + i * 512;
        int tile = lin >> 10, idx = lin & 1023;
        int row = idx >> 4, pc = idx & 15;
        const float* src = (tile ? l2base : l1base) + (size_t)row * L_ + pc * 4;
        cp16(ub + (tile ? FRAW2_(0) : FRAW1_(0)) + idx * 16, src);
    }
    CP_COMMIT();
    __syncthreads();                              // sStat visible

    const int w = t >> 5, lane = t & 31;
    const int wm = (w >> 2) << 4;                 // 0,16,32,48
    const int wn = (w & 3) << 4;                  // 0,16,32,48
    const int gid = lane >> 2, tig = lane & 3;

    __nv_bfloat16* sAh = (__nv_bfloat16*)(smb + FSAH_);
    __nv_bfloat16* sAl = (__nv_bfloat16*)(smb + FSAL_);

    float acc[2][4] = {};

    for (int kt = 0; kt < 16; kt++) {
        const int k0 = kt << 6;
        const int cur = kt & 1;

        // a) Issue V(kt) into single buffer (freed by prev end-of-iter sync)
        #pragma unroll
        for (int i = 0; i < 2; i++) {
            int lin = t + i * 512;                // 1024 chunks: 2 x 64 rows x 8
            int tile = lin >> 9, r = (lin >> 3) & 63, pc = lin & 7;
            const __nv_bfloat16* vs =
                (tile ? g_Vtl : g_Vth) + ((size_t)bh * DK_ + r) * L_ + k0 + pc * 8;
            cp16(ub + (tile ? FVL_ : FVH_) + r * 144 + pc * 16, vs);
        }
        CP_COMMIT();

        // b) Wait raw(kt) (issued one iteration ago), V still pending
        CP_WAIT(1);

        // c) Transform raw(kt): exp-combine, stream attn, split to smem.
        //    raw reads are self-loaded per-thread (same lin mapping) — no barrier.
        {
            const float* r1 = (const float*)(smb + FRAW1_(cur));
            const float* r2 = (const float*)(smb + FRAW2_(cur));
            #pragma unroll
            for (int i = 0; i < 2; i++) {
                int lin = t + i * 512;            // 1024 float4 slots
                int row = lin >> 4, pc = lin & 15;
                float4 x1 = *(const float4*)(r1 + lin * 4);
                float4 x2 = *(const float4*)(r2 + lin * 4);
                float M1 = sStat[row], I1 = sStat[64 + row];
                float M2 = sStat[128 + row], I2 = sStat[192 + row];
                float f[4];
                f[0] = __expf(x1.x - M1) * I1 + __expf(x2.x - M2) * I2;
                f[1] = __expf(x1.y - M1) * I1 + __expf(x2.y - M2) * I2;
                f[2] = __expf(x1.z - M1) * I1 + __expf(x2.z - M2) * I2;
                f[3] = __expf(x1.w - M1) * I1 + __expf(x2.w - M2) * I2;
                __stcs((float4*)(l2base + (size_t)row * L_ + k0 + pc * 4),
                       make_float4(f[0], f[1], f[2], f[3]));
                uint2 hp, lp;
                split_pack4(f, hp, lp);
                *(uint2*)(sAh + row * ST + pc * 4) = hp;
                *(uint2*)(sAl + row * ST + pc * 4) = lp;
            }
        }

        // d) Prefetch raw(kt+1) into alternate buffer
        if (kt < 15) {
            const int nxt = cur ^ 1;
            const int kn = k0 + 64;
            #pragma unroll
            for (int i = 0; i < 4; i++) {
                int lin = t + i * 512;
                int tile = lin >> 10, idx = lin & 1023;
                int row = idx >> 4, pc = idx & 15;
                const float* src = (tile ? l2base : l1base) + (size_t)row * L_ + kn + pc * 4;
                cp16(ub + (tile ? FRAW2_(nxt) : FRAW1_(nxt)) + idx * 16, src);
            }
            CP_COMMIT();
            // e) Wait V(kt); raw(kt+1) stays in flight
            CP_WAIT(1);
        } else {
            CP_WAIT(0);
        }
        __syncthreads();                          // split + V visible to all warps

        // g) MMA on split(kt) x V(kt)
        const __nv_bfloat16* sVh = (const __nv_bfloat16*)(smb + FVH_);
        const __nv_bfloat16* sVl = (const __nv_bfloat16*)(smb + FVL_);
        #pragma unroll
        for (int k1 = 0; k1 < 64; k1 += 16) {
            uint32_t ah[4], al[4];
            {
                int r = wm + gid;
                ah[0] = *(const uint32_t*)(sAh + r * ST + k1 + tig * 2);
                ah[1] = *(const uint32_t*)(sAh + (r + 8) * ST + k1 + tig * 2);
                ah[2] = *(const uint32_t*)(sAh + r * ST + k1 + tig * 2 + 8);
                ah[3] = *(const uint32_t*)(sAh + (r + 8) * ST + k1 + tig * 2 + 8);
                al[0] = *(const uint32_t*)(sAl + r * ST + k1 + tig * 2);
                al[1] = *(const uint32_t*)(sAl + (r + 8) * ST + k1 + tig * 2);
                al[2] = *(const uint32_t*)(sAl + r * ST + k1 + tig * 2 + 8);
                al[3] = *(const uint32_t*)(sAl + (r + 8) * ST + k1 + tig * 2 + 8);
            }
            uint32_t bhf[2][2], blf[2][2];
            #pragma unroll
            for (int j = 0; j < 2; j++) {
                int r = wn + j * 8 + gid;
                bhf[j][0] = *(const uint32_t*)(sVh + r * ST + k1 + tig * 2);
                bhf[j][1] = *(const uint32_t*)(sVh + r * ST + k1 + tig * 2 + 8);
                blf[j][0] = *(const uint32_t*)(sVl + r * ST + k1 + tig * 2);
                blf[j][1] = *(const uint32_t*)(sVl + r * ST + k1 + tig * 2 + 8);
            }
            #pragma unroll
            for (int j = 0; j < 2; j++) {
                mma_bf16(acc[j], ah, bhf[j][0], bhf[j][1]);
                mma_bf16(acc[j], ah, blf[j][0], blf[j][1]);
                mma_bf16(acc[j], al, bhf[j][0], bhf[j][1]);
            }
        }
        __syncthreads();                          // buffers free for next iter
    }

    #pragma unroll
    for (int j = 0; j < 2; j++) {
        int m = q0 + wm + gid;
        int n = wn + j * 8 + tig * 2;
        *(float2*)(ctx + ((size_t)bh * L_ + m) * DK_ + n) =
            make_float2(acc[j][0], acc[j][1]);
        *(float2*)(ctx + ((size_t)bh * L_ + m + 8) * DK_ + n) =
            make_float2(acc[j][2], acc[j][3]);
    }
}

// ---------------------------------------------------------------------------
extern "C" void kernel_launch(void* const* d_in, const int* in_sizes, int n_in,
                              void* d_out, int out_size) {
    const float* Q = (const float*)d_in[0];
    const float* K = (const float*)d_in[1];
    const float* V = (const float*)d_in[2];
    const float* W = (const float*)d_in[3];
    float* ctx  = (float*)d_out;                    // [B,H,L,Dv]
    float* attn = ctx + (size_t)BH_ * L_ * DK_;     // [B,H,L,L]

    // Prep
    cat_kernel<<<BH_ * L_ * 32 / 256, 256>>>(Q, K);
    wsplit_kernel<<<H_ * L_ * 32 / 256, 256>>>(W);
    vtrans_kernel<<<dim3(L_ / 64, BH_), 256>>>(V);

    // n-persistent logits (+ in-kernel row stats)
    const int smem0 = 6 * 128 * (64 + 8) * 2;    // 110,592
    const int smem1 = 6 * 128 * (128 + 8) * 2;   // 208,896
    cudaFuncSetAttribute(mm_logits_kernel<0>,
                         cudaFuncAttributeMaxDynamicSharedMemorySize, smem0);
    cudaFuncSetAttribute(mm_logits_kernel<1>,
                         cudaFuncAttributeMaxDynamicSharedMemorySize, smem1);
    mm_logits_kernel<0><<<dim3(8, BH_), 256, smem0>>>(attn);
    mm_logits_kernel<1><<<dim3(8, BH_), 256, smem1>>>(attn);

    // Fused softmax-add + AV (64-row tiles, 2 CTAs/SM)
    cudaFuncSetAttribute(fused_attn_av_kernel,
                         cudaFuncAttributeMaxDynamicSharedMemorySize, FSMEM_);
    fused_attn_av_kernel<<<dim3(16, BH_), 512, FSMEM_>>>(attn, ctx);
}